// round 14
// baseline (speedup 1.0000x reference)
#include <cuda_runtime.h>

// Shapes (fixed for this problem)
#define BB   8
#define LL   200
#define HIDD 256
#define NH   8
#define DHH  32
#define NEGV (-4294967295.0f)   // -2^32 + 1, matches reference padding value

// Scratch (device globals: allocation-free rule)
__device__ float g_Qp[BB * LL * HIDD];
__device__ float g_Ks[BB * LL * HIDD];   // K-proj + abs_pos_K  (folded)
__device__ float g_Vs[BB * LL * HIDD];   // V-proj + abs_pos_V  (folded)

// ---------------------------------------------------------------------------
// Projection GEMM:  Y = X @ W^T + bias (+ optional abs_pos fold)
// M=1600, N=256, K=256.  grid (25, 4, 3): z selects Q/K/V. block = 256 thr.
// BM=BN=64, BK=32. 4x4 register micro-tile.  (fp32-FFMA roofline-bound.)
// ---------------------------------------------------------------------------
__global__ __launch_bounds__(256) void proj_kernel(
    const float* __restrict__ queries, const float* __restrict__ keys,
    const float* __restrict__ Wq, const float* __restrict__ bq,
    const float* __restrict__ Wk, const float* __restrict__ bk,
    const float* __restrict__ Wv, const float* __restrict__ bv,
    const float* __restrict__ apK, const float* __restrict__ apV)
{
    const int which = blockIdx.z;
    const float* X    = (which == 0) ? queries : keys;
    const float* W    = (which == 0) ? Wq : (which == 1) ? Wk : Wv;
    const float* bias = (which == 0) ? bq : (which == 1) ? bk : bv;
    const float* fold = (which == 0) ? (const float*)0 : (which == 1) ? apK : apV;
    float* Y          = (which == 0) ? g_Qp : (which == 1) ? g_Ks : g_Vs;

    __shared__ float As[32][65];   // [k][m], padded
    __shared__ float Bs[32][65];   // [k][n], padded

    const int tid = threadIdx.x;
    const int tx = tid & 15, ty = tid >> 4;
    const int row0 = blockIdx.x * 64, col0 = blockIdx.y * 64;

    const int lr  = tid >> 2;          // 0..63 (tile row to load)
    const int lc8 = (tid & 3) * 8;     // 0,8,16,24 (k-offset)

    float acc[4][4] = {};

    for (int kt = 0; kt < HIDD; kt += 32) {
        float4 av0 = *(const float4*)&X[(row0 + lr) * HIDD + kt + lc8];
        float4 av1 = *(const float4*)&X[(row0 + lr) * HIDD + kt + lc8 + 4];
        float4 bw0 = *(const float4*)&W[(col0 + lr) * HIDD + kt + lc8];
        float4 bw1 = *(const float4*)&W[(col0 + lr) * HIDD + kt + lc8 + 4];
        As[lc8 + 0][lr] = av0.x;  As[lc8 + 1][lr] = av0.y;
        As[lc8 + 2][lr] = av0.z;  As[lc8 + 3][lr] = av0.w;
        As[lc8 + 4][lr] = av1.x;  As[lc8 + 5][lr] = av1.y;
        As[lc8 + 6][lr] = av1.z;  As[lc8 + 7][lr] = av1.w;
        Bs[lc8 + 0][lr] = bw0.x;  Bs[lc8 + 1][lr] = bw0.y;
        Bs[lc8 + 2][lr] = bw0.z;  Bs[lc8 + 3][lr] = bw0.w;
        Bs[lc8 + 4][lr] = bw1.x;  Bs[lc8 + 5][lr] = bw1.y;
        Bs[lc8 + 6][lr] = bw1.z;  Bs[lc8 + 7][lr] = bw1.w;
        __syncthreads();
        #pragma unroll
        for (int kk = 0; kk < 32; kk++) {
            float a[4], b[4];
            #pragma unroll
            for (int i = 0; i < 4; i++) a[i] = As[kk][ty * 4 + i];
            #pragma unroll
            for (int j = 0; j < 4; j++) b[j] = Bs[kk][tx * 4 + j];
            #pragma unroll
            for (int i = 0; i < 4; i++)
                #pragma unroll
                for (int j = 0; j < 4; j++)
                    acc[i][j] += a[i] * b[j];
        }
        __syncthreads();
    }

    #pragma unroll
    for (int i = 0; i < 4; i++) {
        const int r = row0 + ty * 4 + i;
        #pragma unroll
        for (int j = 0; j < 4; j++) {
            const int cc = col0 + tx * 4 + j;
            float v = acc[i][j] + bias[cc];
            if (fold) v += fold[r * HIDD + cc];
            Y[r * HIDD + cc] = v;
        }
    }
}

// ---------------------------------------------------------------------------
// Attention, single-pass online softmax. One CTA per (q, b), q heaviest-first.
// 256 threads: warp w = head w, lane l = channel 32w+l = tid.
// Per k: 4 scalar loads (Ks, TMK, Vs, TMV at this channel) -> each warp
// instruction touches exactly one 128B line. Logit via 5-shuffle butterfly
// (all lanes), then flash-style online update of (m, s, acc). No aw array,
// no inter-phase barriers. Masked k skipped (weight == 0 in reference);
// fully-masked row -> uniform 1/LL average (matches reference exactly).
// ---------------------------------------------------------------------------
__global__ __launch_bounds__(256) void attn_kernel(
    const float* __restrict__ tmK, const float* __restrict__ tmV,
    const int* __restrict__ time_mask, const int* __restrict__ attn_mask,
    float* __restrict__ out)
{
    const int q = (LL - 1) - blockIdx.x;   // heaviest (largest k-range) first
    const int b = blockIdx.y;
    const int tid = threadIdx.x;
    const int w = tid >> 5;        // warp
    const int l = tid & 31;        // lane
    const int c = tid;             // channel 0..255 (= 32*head + dim)

    __shared__ int klist[LL];
    __shared__ int s_nk, s_k0, s_contig;

    if (w == 0) {
        // Warp 0: compact unmasked k indices (order-preserving ballot scan)
        const int tmw = time_mask[b * LL + q];
        int base = 0;
        #pragma unroll
        for (int c0 = 0; c0 < 224; c0 += 32) {
            const int k = c0 + l;
            const bool un = (k < LL) && (tmw == 0) && (attn_mask[q * LL + k] == 0);
            const unsigned bal = __ballot_sync(0xffffffffu, un);
            if (un) klist[base + __popc(bal & ((1u << l) - 1u))] = k;
            base += __popc(bal);
        }
        if (l == 0) {
            s_nk = base;
            if (base > 0) {
                const int k0 = klist[0];
                s_k0 = k0;
                s_contig = (klist[base - 1] - k0 == base - 1);
            } else {
                s_k0 = 0;
                s_contig = 1;
            }
        }
    }
    __syncthreads();
    const int nk     = s_nk;
    const int k0     = s_k0;
    const int contig = s_contig;

    const float* __restrict__ pV  = g_Vs + (size_t)(b * LL) * HIDD + c;
    const float* __restrict__ pTV = tmV + (size_t)(b * LL + q) * LL * HIDD + c;
    float* __restrict__ po = out + (size_t)(b * LL + q) * HIDD + c;

    // Degenerate fully-masked row: softmax uniform over ALL k.
    if (nk == 0) {
        float acc = 0.f;
        #pragma unroll 4
        for (int k = 0; k < LL; k++)
            acc += pV[(size_t)k * HIDD] + __ldcs(pTV + (size_t)k * HIDD);
        *po = acc * (1.0f / LL);
        return;
    }

    const float qv = g_Qp[(size_t)(b * LL + q) * HIDD + c];
    const float* __restrict__ pK  = g_Ks + (size_t)(b * LL) * HIDD + c;
    const float* __restrict__ pTK = tmK + (size_t)(b * LL + q) * LL * HIDD + c;
    const float scale = 0.17677669529663687f;   // 1/sqrt(32)

    float m = -3.402823466e38f;
    float s = 0.f;
    float acc = 0.f;

    if (contig) {
        const float* __restrict__ cK  = pK  + (size_t)k0 * HIDD;
        const float* __restrict__ cV  = pV  + (size_t)k0 * HIDD;
        const float* __restrict__ cTK = pTK + (size_t)k0 * HIDD;
        const float* __restrict__ cTV = pTV + (size_t)k0 * HIDD;
        #pragma unroll 4
        for (int i = 0; i < nk; i++) {
            const float ks = cK[(size_t)i * HIDD];
            const float tk = __ldcs(cTK + (size_t)i * HIDD);
            const float vs = cV[(size_t)i * HIDD];
            const float tv = __ldcs(cTV + (size_t)i * HIDD);
            float p = qv * (ks + tk);
            p += __shfl_xor_sync(0xffffffffu, p, 16);
            p += __shfl_xor_sync(0xffffffffu, p, 8);
            p += __shfl_xor_sync(0xffffffffu, p, 4);
            p += __shfl_xor_sync(0xffffffffu, p, 2);
            p += __shfl_xor_sync(0xffffffffu, p, 1);
            const float logit = p * scale;
            const float val = vs + tv;
            const float mn  = fmaxf(m, logit);
            const float cor = __expf(m - mn);      // 0 on first iteration
            const float pe  = __expf(logit - mn);
            s   = s * cor + pe;
            acc = acc * cor + pe * val;
            m   = mn;
        }
    } else {
        #pragma unroll 2
        for (int i = 0; i < nk; i++) {
            const int k = klist[i];
            const float ks = pK[(size_t)k * HIDD];
            const float tk = __ldcs(pTK + (size_t)k * HIDD);
            const float vs = pV[(size_t)k * HIDD];
            const float tv = __ldcs(pTV + (size_t)k * HIDD);
            float p = qv * (ks + tk);
            p += __shfl_xor_sync(0xffffffffu, p, 16);
            p += __shfl_xor_sync(0xffffffffu, p, 8);
            p += __shfl_xor_sync(0xffffffffu, p, 4);
            p += __shfl_xor_sync(0xffffffffu, p, 2);
            p += __shfl_xor_sync(0xffffffffu, p, 1);
            const float logit = p * scale;
            const float val = vs + tv;
            const float mn  = fmaxf(m, logit);
            const float cor = __expf(m - mn);
            const float pe  = __expf(logit - mn);
            s   = s * cor + pe;
            acc = acc * cor + pe * val;
            m   = mn;
        }
    }

    *po = acc / s;
}

// ---------------------------------------------------------------------------
extern "C" void kernel_launch(void* const* d_in, const int* in_sizes, int n_in,
                              void* d_out, int out_size)
{
    const float* queries   = (const float*)d_in[0];
    const float* keys      = (const float*)d_in[1];
    const int*   time_mask = (const int*)  d_in[2];
    const int*   attn_mask = (const int*)  d_in[3];
    const float* tmK       = (const float*)d_in[4];
    const float* tmV       = (const float*)d_in[5];
    const float* apK       = (const float*)d_in[6];
    const float* apV       = (const float*)d_in[7];
    // d_in[8] = time_attn (unused by the forward pass)
    const float* Wq        = (const float*)d_in[9];
    const float* bq        = (const float*)d_in[10];
    const float* Wk        = (const float*)d_in[11];
    const float* bk        = (const float*)d_in[12];
    const float* Wv        = (const float*)d_in[13];
    const float* bv        = (const float*)d_in[14];
    float* out = (float*)d_out;

    dim3 pgrid(1600 / 64, HIDD / 64, 3);   // (25, 4, 3)
    proj_kernel<<<pgrid, 256>>>(queries, keys, Wq, bq, Wk, bk, Wv, bv, apK, apV);

    dim3 agrid(LL, BB);                     // (200, 8)
    attn_kernel<<<agrid, 256>>>(tmK, tmV, time_mask, attn_mask, out);
}

// round 15
// speedup vs baseline: 1.1762x; 1.1762x over previous
#include <cuda_runtime.h>
#include <cstdint>

// Shapes (fixed for this problem)
#define BB   8
#define LL   200
#define HIDD 256
#define NH   8
#define DHH  32
#define NEGV (-4294967295.0f)   // -2^32 + 1, matches reference padding value

// cp.async pipeline geometry
#define NS   4                  // ring stages
#define RPS  8                  // k-rows per stage (8 rows x 1KB = 8KB)
#define STF4 (RPS * 64)         // float4s per stage (512)

// Scratch (device globals: allocation-free rule)
__device__ float g_Qp[BB * LL * HIDD];
__device__ float g_Ks[BB * LL * HIDD];   // K-proj + abs_pos_K  (folded)
__device__ float g_Vs[BB * LL * HIDD];   // V-proj + abs_pos_V  (folded)

#define CP_ASYNC16(sa, ga) \
    asm volatile("cp.async.cg.shared.global [%0], [%1], 16;\n" :: "r"(sa), "l"(ga))
#define CP_COMMIT() asm volatile("cp.async.commit_group;\n" ::: "memory")
#define CP_WAIT(n)  asm volatile("cp.async.wait_group %0;\n" :: "n"(n) : "memory")

// ---------------------------------------------------------------------------
// Projection GEMM:  Y = X @ W^T + bias (+ optional abs_pos fold)
// M=1600, N=256, K=256.  grid (25, 4, 3): z selects Q/K/V. block = 256 thr.
// BM=BN=64, BK=32. 4x4 register micro-tile.  (fp32-FFMA roofline-bound.)
// ---------------------------------------------------------------------------
__global__ __launch_bounds__(256) void proj_kernel(
    const float* __restrict__ queries, const float* __restrict__ keys,
    const float* __restrict__ Wq, const float* __restrict__ bq,
    const float* __restrict__ Wk, const float* __restrict__ bk,
    const float* __restrict__ Wv, const float* __restrict__ bv,
    const float* __restrict__ apK, const float* __restrict__ apV)
{
    const int which = blockIdx.z;
    const float* X    = (which == 0) ? queries : keys;
    const float* W    = (which == 0) ? Wq : (which == 1) ? Wk : Wv;
    const float* bias = (which == 0) ? bq : (which == 1) ? bk : bv;
    const float* fold = (which == 0) ? (const float*)0 : (which == 1) ? apK : apV;
    float* Y          = (which == 0) ? g_Qp : (which == 1) ? g_Ks : g_Vs;

    __shared__ float As[32][65];   // [k][m], padded
    __shared__ float Bs[32][65];   // [k][n], padded

    const int tid = threadIdx.x;
    const int tx = tid & 15, ty = tid >> 4;
    const int row0 = blockIdx.x * 64, col0 = blockIdx.y * 64;

    const int lr  = tid >> 2;          // 0..63 (tile row to load)
    const int lc8 = (tid & 3) * 8;     // 0,8,16,24 (k-offset)

    float acc[4][4] = {};

    for (int kt = 0; kt < HIDD; kt += 32) {
        float4 av0 = *(const float4*)&X[(row0 + lr) * HIDD + kt + lc8];
        float4 av1 = *(const float4*)&X[(row0 + lr) * HIDD + kt + lc8 + 4];
        float4 bw0 = *(const float4*)&W[(col0 + lr) * HIDD + kt + lc8];
        float4 bw1 = *(const float4*)&W[(col0 + lr) * HIDD + kt + lc8 + 4];
        As[lc8 + 0][lr] = av0.x;  As[lc8 + 1][lr] = av0.y;
        As[lc8 + 2][lr] = av0.z;  As[lc8 + 3][lr] = av0.w;
        As[lc8 + 4][lr] = av1.x;  As[lc8 + 5][lr] = av1.y;
        As[lc8 + 6][lr] = av1.z;  As[lc8 + 7][lr] = av1.w;
        Bs[lc8 + 0][lr] = bw0.x;  Bs[lc8 + 1][lr] = bw0.y;
        Bs[lc8 + 2][lr] = bw0.z;  Bs[lc8 + 3][lr] = bw0.w;
        Bs[lc8 + 4][lr] = bw1.x;  Bs[lc8 + 5][lr] = bw1.y;
        Bs[lc8 + 6][lr] = bw1.z;  Bs[lc8 + 7][lr] = bw1.w;
        __syncthreads();
        #pragma unroll
        for (int kk = 0; kk < 32; kk++) {
            float a[4], b[4];
            #pragma unroll
            for (int i = 0; i < 4; i++) a[i] = As[kk][ty * 4 + i];
            #pragma unroll
            for (int j = 0; j < 4; j++) b[j] = Bs[kk][tx * 4 + j];
            #pragma unroll
            for (int i = 0; i < 4; i++)
                #pragma unroll
                for (int j = 0; j < 4; j++)
                    acc[i][j] += a[i] * b[j];
        }
        __syncthreads();
    }

    #pragma unroll
    for (int i = 0; i < 4; i++) {
        const int r = row0 + ty * 4 + i;
        #pragma unroll
        for (int j = 0; j < 4; j++) {
            const int cc = col0 + tx * 4 + j;
            float v = acc[i][j] + bias[cc];
            if (fold) v += fold[r * HIDD + cc];
            Y[r * HIDD + cc] = v;
        }
    }
}

// ---------------------------------------------------------------------------
// Attention: one CTA per (q, b); q heaviest-first. 256 threads.
// R11 two-phase structure, with the DRAM streams (tmK phase 1, tmV phase 3)
// staged through a 4-stage x 8-row cp.async ring: in-flight bytes are
// decoupled from registers/occupancy. Ks/Vs (L2-hot) stay direct loads.
// Phase-3 pipeline prologue issues BEFORE the softmax (overlap).
// Mask handling: ballot compaction; contiguous range fast path; generic
// klist fallback; fully-masked row -> all-NEGV softmax = uniform weights.
// ---------------------------------------------------------------------------
__global__ __launch_bounds__(256) void attn_kernel(
    const float* __restrict__ tmK, const float* __restrict__ tmV,
    const int* __restrict__ time_mask, const int* __restrict__ attn_mask,
    float* __restrict__ out)
{
    const int q = (LL - 1) - blockIdx.x;   // heaviest (largest k-range) first
    const int b = blockIdx.y;
    const int tid = threadIdx.x;
    const int w = tid >> 5;        // warp
    const int l = tid & 31;        // lane

    __shared__ float4 buf[NS][STF4];       // 32 KB streaming ring
    __shared__ float  aw[NH][LL];
    __shared__ int    klist[LL];
    __shared__ int    s_nk, s_k0, s_contig;
    __shared__ float4 red[4][64];

    if (w == 0) {
        // Warp 0: compact unmasked k indices (order-preserving ballot scan)
        const int tmw = time_mask[b * LL + q];
        int base = 0;
        #pragma unroll
        for (int c0 = 0; c0 < 224; c0 += 32) {
            const int k = c0 + l;
            const bool un = (k < LL) && (tmw == 0) && (attn_mask[q * LL + k] == 0);
            const unsigned bal = __ballot_sync(0xffffffffu, un);
            if (un) klist[base + __popc(bal & ((1u << l) - 1u))] = k;
            base += __popc(bal);
        }
        if (l == 0) {
            s_nk = base;
            if (base > 0) {
                const int k0 = klist[0];
                s_k0 = k0;
                s_contig = (klist[base - 1] - k0 == base - 1);
            } else {
                s_k0 = 0;
                s_contig = 1;
            }
        }
    } else {
        // Warps 1-7: prefill logits with the masked value
        for (int idx = tid - 32; idx < NH * LL; idx += 224)
            (&aw[0][0])[idx] = NEGV;
    }
    __syncthreads();
    const int nk     = s_nk;
    const int k0     = s_k0;
    const int contig = s_contig;

    const float* __restrict__ Qp = g_Qp + (size_t)(b * LL + q) * HIDD;
    const float4 q0 = *(const float4*)(Qp + 4 * l);
    const float4 q1 = *(const float4*)(Qp + 128 + 4 * l);

    const float* __restrict__ Ks  = g_Ks + (size_t)(b * LL) * HIDD;
    const float* __restrict__ TMK = tmK + (size_t)(b * LL + q) * LL * HIDD;
    const float  scale = 0.17677669529663687f;   // 1/sqrt(32)

    const int  seg = l >> 3;           // 0..3: p0 -> head seg, p1 -> head 4+seg
    const bool wr  = (l & 7) == 0;

    const uint32_t sbuf = (uint32_t)__cvta_generic_to_shared(&buf[0][0]);

    // ---- Phase 1: logits ----
    if (contig) {
        const float* __restrict__ baseT = TMK + (size_t)k0 * HIDD;  // row i = k0+i
        const int nst = (nk + RPS - 1) / RPS;
        // prologue: issue stages 0..NS-2
        #pragma unroll
        for (int ps = 0; ps < NS - 1; ps++) {
            if (ps < nst) {
                #pragma unroll
                for (int u = 0; u < 2; u++) {
                    const int off = u * 256 + tid;
                    const int r = ps * RPS + (off >> 6);
                    if (r < nk)
                        CP_ASYNC16(sbuf + (uint32_t)(((ps & (NS - 1)) * STF4 + off) * 16),
                                   (const void*)((const float4*)(baseT + (size_t)r * HIDD) + (off & 63)));
                }
            }
            CP_COMMIT();
        }
        for (int s = 0; s < nst; s++) {
            CP_WAIT(NS - 2);
            __syncthreads();
            const int i = s * RPS + w;
            if (i < nk) {
                const int k = k0 + i;
                const float4* trow = &buf[s & (NS - 1)][w * 64];
                const float4 t0 = trow[l];
                const float4 t1 = trow[32 + l];
                const float4 a0 = *(const float4*)(Ks + (size_t)k * HIDD + 4 * l);
                const float4 a1 = *(const float4*)(Ks + (size_t)k * HIDD + 128 + 4 * l);
                float p0 = q0.x * (a0.x + t0.x) + q0.y * (a0.y + t0.y)
                         + q0.z * (a0.z + t0.z) + q0.w * (a0.w + t0.w);
                float p1 = q1.x * (a1.x + t1.x) + q1.y * (a1.y + t1.y)
                         + q1.z * (a1.z + t1.z) + q1.w * (a1.w + t1.w);
                p0 += __shfl_xor_sync(0xffffffffu, p0, 1);
                p0 += __shfl_xor_sync(0xffffffffu, p0, 2);
                p0 += __shfl_xor_sync(0xffffffffu, p0, 4);
                p1 += __shfl_xor_sync(0xffffffffu, p1, 1);
                p1 += __shfl_xor_sync(0xffffffffu, p1, 2);
                p1 += __shfl_xor_sync(0xffffffffu, p1, 4);
                if (wr) { aw[seg][k] = p0 * scale; aw[4 + seg][k] = p1 * scale; }
            }
            const int ns_ = s + NS - 1;
            if (ns_ < nst) {
                #pragma unroll
                for (int u = 0; u < 2; u++) {
                    const int off = u * 256 + tid;
                    const int r = ns_ * RPS + (off >> 6);
                    if (r < nk)
                        CP_ASYNC16(sbuf + (uint32_t)(((ns_ & (NS - 1)) * STF4 + off) * 16),
                                   (const void*)((const float4*)(baseT + (size_t)r * HIDD) + (off & 63)));
                }
            }
            CP_COMMIT();
        }
        CP_WAIT(0);
    } else {
        #pragma unroll 2
        for (int i = w; i < nk; i += 8) {
            const int k = klist[i];
            const float4 a0 = *(const float4*)(Ks + (size_t)k * HIDD + 4 * l);
            const float4 a1 = *(const float4*)(Ks + (size_t)k * HIDD + 128 + 4 * l);
            const float4 t0 = __ldcs((const float4*)(TMK + (size_t)k * HIDD + 4 * l));
            const float4 t1 = __ldcs((const float4*)(TMK + (size_t)k * HIDD + 128 + 4 * l));
            float p0 = q0.x * (a0.x + t0.x) + q0.y * (a0.y + t0.y)
                     + q0.z * (a0.z + t0.z) + q0.w * (a0.w + t0.w);
            float p1 = q1.x * (a1.x + t1.x) + q1.y * (a1.y + t1.y)
                     + q1.z * (a1.z + t1.z) + q1.w * (a1.w + t1.w);
            p0 += __shfl_xor_sync(0xffffffffu, p0, 1);
            p0 += __shfl_xor_sync(0xffffffffu, p0, 2);
            p0 += __shfl_xor_sync(0xffffffffu, p0, 4);
            p1 += __shfl_xor_sync(0xffffffffu, p1, 1);
            p1 += __shfl_xor_sync(0xffffffffu, p1, 2);
            p1 += __shfl_xor_sync(0xffffffffu, p1, 4);
            if (wr) { aw[seg][k] = p0 * scale; aw[4 + seg][k] = p1 * scale; }
        }
    }
    __syncthreads();

    // Fully-masked row: all-NEGV logits -> softmax is uniform over ALL k
    // (matches reference exactly). Visit every k in phase 3.
    const int n3  = (nk == 0) ? LL : nk;
    const int k03 = (nk == 0) ? 0  : k0;
    const float* __restrict__ TMV = tmV + (size_t)(b * LL + q) * LL * HIDD;
    const float* __restrict__ baseV3 = TMV + (size_t)k03 * HIDD;
    const int nst3 = (n3 + RPS - 1) / RPS;

    // Phase-3 pipeline prologue BEFORE softmax: overlap softmax with DRAM.
    if (contig) {
        #pragma unroll
        for (int ps = 0; ps < NS - 1; ps++) {
            if (ps < nst3) {
                #pragma unroll
                for (int u = 0; u < 2; u++) {
                    const int off = u * 256 + tid;
                    const int r = ps * RPS + (off >> 6);
                    if (r < n3)
                        CP_ASYNC16(sbuf + (uint32_t)(((ps & (NS - 1)) * STF4 + off) * 16),
                                   (const void*)((const float4*)(baseV3 + (size_t)r * HIDD) + (off & 63)));
                }
            }
            CP_COMMIT();
        }
    }

    // ---- Phase 2: per-head softmax (warp w = head w) ----
    {
        float vals[7];
        float mx = -3.402823466e38f;
        #pragma unroll
        for (int i = 0; i < 7; i++) {
            const int k = l + 32 * i;
            float v = (k < LL) ? aw[w][k] : -3.402823466e38f;
            vals[i] = v;
            mx = fmaxf(mx, v);
        }
        #pragma unroll
        for (int o = 16; o > 0; o >>= 1)
            mx = fmaxf(mx, __shfl_xor_sync(0xffffffffu, mx, o));
        float s = 0.f;
        #pragma unroll
        for (int i = 0; i < 7; i++) {
            const int k = l + 32 * i;
            if (k < LL) { vals[i] = __expf(vals[i] - mx); s += vals[i]; }
        }
        #pragma unroll
        for (int o = 16; o > 0; o >>= 1)
            s += __shfl_xor_sync(0xffffffffu, s, o);
        const float inv = 1.0f / s;
        #pragma unroll
        for (int i = 0; i < 7; i++) {
            const int k = l + 32 * i;
            if (k < LL) aw[w][k] = vals[i] * inv;
        }
    }
    __syncthreads();

    // ---- Phase 3: weighted value accumulation (float4 per thread) ----
    const int j  = tid & 63;       // channel group: channels [4j, 4j+4)
    const int kq = tid >> 6;       // k row offset mod 4 within stage-half
    const int h3 = j >> 3;         // head of channels 4j..4j+3
    const float* __restrict__ Vs = g_Vs + (size_t)(b * LL) * HIDD;

    float4 acc = make_float4(0.f, 0.f, 0.f, 0.f);
    if (contig) {
        for (int s = 0; s < nst3; s++) {
            CP_WAIT(NS - 2);
            __syncthreads();
            const int slot = s & (NS - 1);
            const int i0 = s * RPS + kq;
            const int i1 = i0 + 4;
            if (i0 < n3) {
                const float wgt = aw[h3][k03 + i0];
                const float4 t = buf[slot][kq * 64 + j];
                const float4 v = *(const float4*)(Vs + (size_t)(k03 + i0) * HIDD + 4 * j);
                acc.x += wgt * (v.x + t.x);
                acc.y += wgt * (v.y + t.y);
                acc.z += wgt * (v.z + t.z);
                acc.w += wgt * (v.w + t.w);
            }
            if (i1 < n3) {
                const float wgt = aw[h3][k03 + i1];
                const float4 t = buf[slot][(kq + 4) * 64 + j];
                const float4 v = *(const float4*)(Vs + (size_t)(k03 + i1) * HIDD + 4 * j);
                acc.x += wgt * (v.x + t.x);
                acc.y += wgt * (v.y + t.y);
                acc.z += wgt * (v.z + t.z);
                acc.w += wgt * (v.w + t.w);
            }
            const int ns_ = s + NS - 1;
            if (ns_ < nst3) {
                #pragma unroll
                for (int u = 0; u < 2; u++) {
                    const int off = u * 256 + tid;
                    const int r = ns_ * RPS + (off >> 6);
                    if (r < n3)
                        CP_ASYNC16(sbuf + (uint32_t)(((ns_ & (NS - 1)) * STF4 + off) * 16),
                                   (const void*)((const float4*)(baseV3 + (size_t)r * HIDD) + (off & 63)));
                }
            }
            CP_COMMIT();
        }
        CP_WAIT(0);
    } else {
        #pragma unroll 4
        for (int i = kq; i < n3; i += 4) {
            const int k = klist[i];
            const float wgt = aw[h3][k];
            const float4 v = *(const float4*)(Vs + (size_t)k * HIDD + 4 * j);
            const float4 t = __ldcs((const float4*)(TMV + (size_t)k * HIDD + 4 * j));
            acc.x += wgt * (v.x + t.x);
            acc.y += wgt * (v.y + t.y);
            acc.z += wgt * (v.z + t.z);
            acc.w += wgt * (v.w + t.w);
        }
    }
    red[kq][j] = acc;
    __syncthreads();
    if (kq == 0) {
        const float4 r1 = red[1][j], r2 = red[2][j], r3 = red[3][j];
        acc.x += r1.x + r2.x + r3.x;
        acc.y += r1.y + r2.y + r3.y;
        acc.z += r1.z + r2.z + r3.z;
        acc.w += r1.w + r2.w + r3.w;
        *(float4*)(out + (size_t)(b * LL + q) * HIDD + 4 * j) = acc;
    }
}

// ---------------------------------------------------------------------------
extern "C" void kernel_launch(void* const* d_in, const int* in_sizes, int n_in,
                              void* d_out, int out_size)
{
    const float* queries   = (const float*)d_in[0];
    const float* keys      = (const float*)d_in[1];
    const int*   time_mask = (const int*)  d_in[2];
    const int*   attn_mask = (const int*)  d_in[3];
    const float* tmK       = (const float*)d_in[4];
    const float* tmV       = (const float*)d_in[5];
    const float* apK       = (const float*)d_in[6];
    const float* apV       = (const float*)d_in[7];
    // d_in[8] = time_attn (unused by the forward pass)
    const float* Wq        = (const float*)d_in[9];
    const float* bq        = (const float*)d_in[10];
    const float* Wk        = (const float*)d_in[11];
    const float* bk        = (const float*)d_in[12];
    const float* Wv        = (const float*)d_in[13];
    const float* bv        = (const float*)d_in[14];
    float* out = (float*)d_out;

    dim3 pgrid(1600 / 64, HIDD / 64, 3);   // (25, 4, 3)
    proj_kernel<<<pgrid, 256>>>(queries, keys, Wq, bq, Wk, bk, Wv, bv, apK, apV);

    dim3 agrid(LL, BB);                     // (200, 8)
    attn_kernel<<<agrid, 256>>>(tmK, tmV, time_mask, attn_mask, out);
}

// round 16
// speedup vs baseline: 1.1973x; 1.0180x over previous
#include <cuda_runtime.h>

// Shapes (fixed for this problem)
#define BB   8
#define LL   200
#define HIDD 256
#define NH   8
#define DHH  32
#define NEGV (-4294967295.0f)   // -2^32 + 1, matches reference padding value

// Scratch (device globals: allocation-free rule)
__device__ float g_Qp[BB * LL * HIDD];
__device__ float g_Ks[BB * LL * HIDD];   // K-proj + abs_pos_K  (folded)
__device__ float g_Vs[BB * LL * HIDD];   // V-proj + abs_pos_V  (folded)

// ---------------------------------------------------------------------------
// Projection GEMM:  Y = X @ W^T + bias (+ optional abs_pos fold)
// M=1600, N=256, K=256.  grid (25, 4, 3): z selects Q/K/V. block = 256 thr.
// BM=BN=64, BK=32. 4x4 register micro-tile.  (fp32-FFMA roofline-bound.)
// ---------------------------------------------------------------------------
__global__ __launch_bounds__(256) void proj_kernel(
    const float* __restrict__ queries, const float* __restrict__ keys,
    const float* __restrict__ Wq, const float* __restrict__ bq,
    const float* __restrict__ Wk, const float* __restrict__ bk,
    const float* __restrict__ Wv, const float* __restrict__ bv,
    const float* __restrict__ apK, const float* __restrict__ apV)
{
    const int which = blockIdx.z;
    const float* X    = (which == 0) ? queries : keys;
    const float* W    = (which == 0) ? Wq : (which == 1) ? Wk : Wv;
    const float* bias = (which == 0) ? bq : (which == 1) ? bk : bv;
    const float* fold = (which == 0) ? (const float*)0 : (which == 1) ? apK : apV;
    float* Y          = (which == 0) ? g_Qp : (which == 1) ? g_Ks : g_Vs;

    __shared__ float As[32][65];   // [k][m], padded
    __shared__ float Bs[32][65];   // [k][n], padded

    const int tid = threadIdx.x;
    const int tx = tid & 15, ty = tid >> 4;
    const int row0 = blockIdx.x * 64, col0 = blockIdx.y * 64;

    const int lr  = tid >> 2;          // 0..63 (tile row to load)
    const int lc8 = (tid & 3) * 8;     // 0,8,16,24 (k-offset)

    float acc[4][4] = {};

    for (int kt = 0; kt < HIDD; kt += 32) {
        float4 av0 = *(const float4*)&X[(row0 + lr) * HIDD + kt + lc8];
        float4 av1 = *(const float4*)&X[(row0 + lr) * HIDD + kt + lc8 + 4];
        float4 bw0 = *(const float4*)&W[(col0 + lr) * HIDD + kt + lc8];
        float4 bw1 = *(const float4*)&W[(col0 + lr) * HIDD + kt + lc8 + 4];
        As[lc8 + 0][lr] = av0.x;  As[lc8 + 1][lr] = av0.y;
        As[lc8 + 2][lr] = av0.z;  As[lc8 + 3][lr] = av0.w;
        As[lc8 + 4][lr] = av1.x;  As[lc8 + 5][lr] = av1.y;
        As[lc8 + 6][lr] = av1.z;  As[lc8 + 7][lr] = av1.w;
        Bs[lc8 + 0][lr] = bw0.x;  Bs[lc8 + 1][lr] = bw0.y;
        Bs[lc8 + 2][lr] = bw0.z;  Bs[lc8 + 3][lr] = bw0.w;
        Bs[lc8 + 4][lr] = bw1.x;  Bs[lc8 + 5][lr] = bw1.y;
        Bs[lc8 + 6][lr] = bw1.z;  Bs[lc8 + 7][lr] = bw1.w;
        __syncthreads();
        #pragma unroll
        for (int kk = 0; kk < 32; kk++) {
            float a[4], b[4];
            #pragma unroll
            for (int i = 0; i < 4; i++) a[i] = As[kk][ty * 4 + i];
            #pragma unroll
            for (int j = 0; j < 4; j++) b[j] = Bs[kk][tx * 4 + j];
            #pragma unroll
            for (int i = 0; i < 4; i++)
                #pragma unroll
                for (int j = 0; j < 4; j++)
                    acc[i][j] += a[i] * b[j];
        }
        __syncthreads();
    }

    #pragma unroll
    for (int i = 0; i < 4; i++) {
        const int r = row0 + ty * 4 + i;
        #pragma unroll
        for (int j = 0; j < 4; j++) {
            const int cc = col0 + tx * 4 + j;
            float v = acc[i][j] + bias[cc];
            if (fold) v += fold[r * HIDD + cc];
            Y[r * HIDD + cc] = v;
        }
    }
}

// ---------------------------------------------------------------------------
// Attention: one CTA per (q, b); q remapped heaviest-first. 256 threads.
// Warp 0 compacts unmasked k's (ballot scan) while warps 1-7 prefill NEGV.
// Phase 1 (half-row mapping): warp w owns channel-half (w&1) of k-rows
//   i == (w>>1) mod 4. One query float4 + one (Ks,TMK) float4 pair live per
//   iteration -> minimal registers, single 3-shuffle segmented reduction
//   (8-lane segments = 4 heads per half). Warps 2j/2j+1 share each 1KB row.
// Phase 2: per-head softmax (warp w = head w).
// Phase 3: thread owns float4 channel group j, compact k strided mod 4;
//   identity-list fallback when every k is masked (uniform softmax case).
// ---------------------------------------------------------------------------
__global__ __launch_bounds__(256, 6) void attn_kernel(
    const float* __restrict__ tmK, const float* __restrict__ tmV,
    const int* __restrict__ time_mask, const int* __restrict__ attn_mask,
    float* __restrict__ out)
{
    const int q = (LL - 1) - blockIdx.x;   // heaviest (largest k-range) first
    const int b = blockIdx.y;
    const int tid = threadIdx.x;
    const int w = tid >> 5;        // warp
    const int l = tid & 31;        // lane

    __shared__ float aw[NH][LL];
    __shared__ int   klist[LL];
    __shared__ int   s_nk;
    __shared__ float4 red[4][64];

    if (w == 0) {
        // Warp 0: compact unmasked k indices (order-preserving ballot scan)
        const int tmw = time_mask[b * LL + q];
        int base = 0;
        #pragma unroll
        for (int c0 = 0; c0 < 224; c0 += 32) {
            const int k = c0 + l;
            const bool un = (k < LL) && (tmw == 0) && (attn_mask[q * LL + k] == 0);
            const unsigned bal = __ballot_sync(0xffffffffu, un);
            if (un) klist[base + __popc(bal & ((1u << l) - 1u))] = k;
            base += __popc(bal);
        }
        if (l == 0) s_nk = base;
    } else {
        // Warps 1-7: prefill logits with the masked value
        for (int idx = tid - 32; idx < NH * LL; idx += 224)
            (&aw[0][0])[idx] = NEGV;
    }
    __syncthreads();
    const int nk = s_nk;

    // Half-row mapping for phase 1
    const int half = w & 1;                // channel half: 0 -> heads 0-3
    const int wk   = w >> 1;               // k-index offset mod 4
    const int coff = half * 128 + 4 * l;   // this lane's channel group

    const float* __restrict__ Qp = g_Qp + (size_t)(b * LL + q) * HIDD;
    const float4 qh = *(const float4*)(Qp + coff);

    const float* __restrict__ Ks  = g_Ks + (size_t)(b * LL) * HIDD;
    const float* __restrict__ TMK = tmK + (size_t)(b * LL + q) * LL * HIDD;
    const float  scale = 0.17677669529663687f;   // 1/sqrt(32)

    const int  hseg = half * 4 + (l >> 3);       // head for this 8-lane segment
    const bool wr1  = (l & 7) == 0;

    // ---- Phase 1: logits over compacted k's (half-row per warp) ----
    #pragma unroll 4
    for (int i = wk; i < nk; i += 4) {
        const int k = klist[i];
        const float4 a = *(const float4*)(Ks + (size_t)k * HIDD + coff);
        const float4 t = __ldcs((const float4*)(TMK + (size_t)k * HIDD + coff));
        float p = qh.x * (a.x + t.x) + qh.y * (a.y + t.y)
                + qh.z * (a.z + t.z) + qh.w * (a.w + t.w);
        p += __shfl_xor_sync(0xffffffffu, p, 1);
        p += __shfl_xor_sync(0xffffffffu, p, 2);
        p += __shfl_xor_sync(0xffffffffu, p, 4);
        if (wr1) aw[hseg][k] = p * scale;
    }
    __syncthreads();

    // ---- Phase 2: per-head softmax (warp w = head w) ----
    {
        float vals[7];
        float mx = -3.402823466e38f;
        #pragma unroll
        for (int i = 0; i < 7; i++) {
            const int k = l + 32 * i;
            float v = (k < LL) ? aw[w][k] : -3.402823466e38f;
            vals[i] = v;
            mx = fmaxf(mx, v);
        }
        #pragma unroll
        for (int o = 16; o > 0; o >>= 1)
            mx = fmaxf(mx, __shfl_xor_sync(0xffffffffu, mx, o));
        float s = 0.f;
        #pragma unroll
        for (int i = 0; i < 7; i++) {
            const int k = l + 32 * i;
            if (k < LL) { vals[i] = __expf(vals[i] - mx); s += vals[i]; }
        }
        #pragma unroll
        for (int o = 16; o > 0; o >>= 1)
            s += __shfl_xor_sync(0xffffffffu, s, o);
        const float inv = 1.0f / s;
        #pragma unroll
        for (int i = 0; i < 7; i++) {
            const int k = l + 32 * i;
            if (k < LL) aw[w][k] = vals[i] * inv;
        }
    }
    __syncthreads();

    // Degenerate fully-masked row: softmax is uniform over ALL k -> phase 3
    // must visit every k. Swap in an identity list. (Block-uniform branch.)
    int nk3 = nk;
    if (nk3 == 0) {
        for (int i = tid; i < LL; i += 256) klist[i] = i;
        nk3 = LL;
        __syncthreads();
    }

    // ---- Phase 3: weighted value accumulation (float4 per thread) ----
    const int j  = tid & 63;       // channel group: channels [4j, 4j+4)
    const int kq = tid >> 6;       // k offset mod 4 (uniform per warp)
    const int h3 = j >> 3;         // head of channels 4j..4j+3
    const float* __restrict__ Vs  = g_Vs + (size_t)(b * LL) * HIDD;
    const float* __restrict__ TMV = tmV + (size_t)(b * LL + q) * LL * HIDD;

    float4 acc = make_float4(0.f, 0.f, 0.f, 0.f);
    #pragma unroll 4
    for (int i = kq; i < nk3; i += 4) {
        const int k = klist[i];
        const float wgt = aw[h3][k];
        const float4 v = *(const float4*)(Vs + (size_t)k * HIDD + 4 * j);
        const float4 t = __ldcs((const float4*)(TMV + (size_t)k * HIDD + 4 * j));
        acc.x += wgt * (v.x + t.x);
        acc.y += wgt * (v.y + t.y);
        acc.z += wgt * (v.z + t.z);
        acc.w += wgt * (v.w + t.w);
    }
    red[kq][j] = acc;
    __syncthreads();
    if (kq == 0) {
        const float4 r1 = red[1][j], r2 = red[2][j], r3 = red[3][j];
        acc.x += r1.x + r2.x + r3.x;
        acc.y += r1.y + r2.y + r3.y;
        acc.z += r1.z + r2.z + r3.z;
        acc.w += r1.w + r2.w + r3.w;
        *(float4*)(out + (size_t)(b * LL + q) * HIDD + 4 * j) = acc;
    }
}

// ---------------------------------------------------------------------------
extern "C" void kernel_launch(void* const* d_in, const int* in_sizes, int n_in,
                              void* d_out, int out_size)
{
    const float* queries   = (const float*)d_in[0];
    const float* keys      = (const float*)d_in[1];
    const int*   time_mask = (const int*)  d_in[2];
    const int*   attn_mask = (const int*)  d_in[3];
    const float* tmK       = (const float*)d_in[4];
    const float* tmV       = (const float*)d_in[5];
    const float* apK       = (const float*)d_in[6];
    const float* apV       = (const float*)d_in[7];
    // d_in[8] = time_attn (unused by the forward pass)
    const float* Wq        = (const float*)d_in[9];
    const float* bq        = (const float*)d_in[10];
    const float* Wk        = (const float*)d_in[11];
    const float* bk        = (const float*)d_in[12];
    const float* Wv        = (const float*)d_in[13];
    const float* bv        = (const float*)d_in[14];
    float* out = (float*)d_out;

    dim3 pgrid(1600 / 64, HIDD / 64, 3);   // (25, 4, 3)
    proj_kernel<<<pgrid, 256>>>(queries, keys, Wq, bq, Wk, bk, Wv, bv, apK, apV);

    dim3 agrid(LL, BB);                     // (200, 8)
    attn_kernel<<<agrid, 256>>>(tmK, tmV, time_mask, attn_mask, out);
}